// round 6
// baseline (speedup 1.0000x reference)
#include <cuda_runtime.h>
#include <stdint.h>

// MaxoutDynamic: per row of [nrows, 4096] fp32, zero the 2048 smallest values,
// scale survivors by 4096/2048 = 2.0. Exact rank selection (row median).
//
// Float-domain selection, 16 floats/thread in registers. Two seed pivots
// (+-0.0822 = +-4.2 sigma of the sample-median distribution) counted during
// the load (one packed reduction). Then DUAL-PIVOT secant rounds: two probes
// per round targeting ranks KEEP +- g/16, both counts packed into ONE
// REDUX + ONE barrier. Early exit when any count == 2048 exactly. Key-space
// bisection fallback guarantees termination; ties resolved by index
// (stable-argsort semantics: largest indices survive).

#define FEAT    4096
#define KEEP    2048u
#define THREADS 256
#define EPT     16
#define NWARP   (THREADS / 32)
#define SEED    0.0822f

__device__ __forceinline__ unsigned f2key(unsigned b) {
    return b ^ (((unsigned)((int)b >> 31)) | 0x80000000u);
}
__device__ __forceinline__ float key2f(unsigned k) {
    unsigned b = (k & 0x80000000u) ? (k ^ 0x80000000u) : ~k;
    return __uint_as_float(b);
}

// One-barrier block sum (caller ping-pongs buf).
__device__ __forceinline__ unsigned block_sum(unsigned c, unsigned* buf,
                                              int lane, int warp) {
    c = __reduce_add_sync(0xFFFFFFFFu, c);
    if (lane == 0) buf[warp] = c;
    __syncthreads();
    uint4 a = *reinterpret_cast<const uint4*>(buf);
    uint4 b = *reinterpret_cast<const uint4*>(buf + 4);
    return a.x + a.y + a.z + a.w + b.x + b.y + b.z + b.w;
}

__global__ __launch_bounds__(THREADS, 6)
void maxout_sel_kernel(const float* __restrict__ in, float* __restrict__ out) {
    const int tid  = threadIdx.x;
    const int lane = tid & 31;
    const int warp = tid >> 5;

    const float4* in4  = reinterpret_cast<const float4*>(in)  + (size_t)blockIdx.x * (FEAT / 4);
    float4*       out4 = reinterpret_cast<float4*>(out)       + (size_t)blockIdx.x * (FEAT / 4);

    __shared__ __align__(16) unsigned scnt[2][NWARP];
    int par = 0;

    // Load row + count both seed pivots in the same pass.
    float v[EPT];
    unsigned c1 = 0, c2 = 0;   // c1 = #{v >= -SEED}, c2 = #{v >= +SEED}
#pragma unroll
    for (int j = 0; j < 4; ++j) {
        float4 u = in4[tid + THREADS * j];
        v[4 * j + 0] = u.x; v[4 * j + 1] = u.y;
        v[4 * j + 2] = u.z; v[4 * j + 3] = u.w;
#pragma unroll
        for (int i = 0; i < 4; ++i) {
            float x = v[4 * j + i];
            c1 += (x >= -SEED) ? 1u : 0u;
            c2 += (x >=  SEED) ? 1u : 0u;
        }
    }
    {
        unsigned packed = block_sum((c1 << 13) | c2, scnt[par], lane, warp);
        par ^= 1;
        c1 = packed >> 13;
        c2 = packed & 0x1FFFu;
    }

    float T = 0.0f;
    unsigned cutoff = 0u;
    bool resolved = false;

    unsigned long long klo, khi;
    float vlo = 0.f, vhi = 0.f;
    unsigned c_klo, c_khi;

    if (c1 == KEEP)      { T = -SEED; resolved = true; klo = khi = 0; c_klo = c_khi = 0; }
    else if (c2 == KEEP) { T =  SEED; resolved = true; klo = khi = 0; c_klo = c_khi = 0; }
    else if (c1 < KEEP)  {           // median below -SEED
        klo = 0ULL;                          c_klo = FEAT;
        khi = f2key(__float_as_uint(-SEED)); c_khi = c1; vhi = -SEED;
    } else if (c2 > KEEP) {          // median above +SEED
        klo = f2key(__float_as_uint(SEED));  c_klo = c2; vlo = SEED;
        khi = 0x100000000ULL;                c_khi = 0u;
    } else {                          // median inside [-SEED, SEED]
        klo = f2key(__float_as_uint(-SEED)); c_klo = c1; vlo = -SEED;
        khi = f2key(__float_as_uint( SEED)); c_khi = c2; vhi =  SEED;
    }

    int iter = 0;
    while (!resolved && khi - klo > 1ULL) {
        const bool interp = (iter < 8) && klo != 0ULL && khi != 0x100000000ULL;
        unsigned g = c_klo - c_khi;

        if (interp && g > 4u && khi - klo > 2ULL) {
            // Dual-pivot secant: target ranks KEEP +- D.
            unsigned D = g >> 4; if (D == 0u) D = 1u;
            float denom = (float)g;
            float fr1 = ((float)c_klo - (float)(KEEP + D)) / denom;  // lower value
            float fr2 = ((float)c_klo - (float)(KEEP - D)) / denom;  // higher value
            unsigned pk1 = f2key(__float_as_uint(vlo + (vhi - vlo) * fr1));
            unsigned pk2 = f2key(__float_as_uint(vlo + (vhi - vlo) * fr2));
            if ((unsigned long long)pk1 <= klo) pk1 = (unsigned)(klo + 1ULL);
            if ((unsigned long long)pk1 >= khi) pk1 = (unsigned)(khi - 1ULL);
            if (pk2 <= pk1) pk2 = pk1 + 1u;
            if ((unsigned long long)pk2 >= khi) pk2 = (unsigned)(khi - 1ULL);

            if (pk2 > pk1) {   // genuine dual probe
                float p1 = key2f(pk1), p2 = key2f(pk2);
                unsigned n = 0;
#pragma unroll
                for (int i = 0; i < EPT; ++i) {
                    float x = v[i];
                    n += (x >= p1) ? (1u << 13) : 0u;
                    n += (x >= p2) ? 1u : 0u;
                }
                n = block_sum(n, scnt[par], lane, warp);
                par ^= 1;
                unsigned n1 = n >> 13, n2 = n & 0x1FFFu;   // n1 >= n2

                if (n1 == KEEP)      { T = p1; resolved = true; break; }
                else if (n2 == KEEP) { T = p2; resolved = true; break; }
                else if (n2 > KEEP)  { klo = pk2; c_klo = n2; vlo = p2; }
                else if (n1 < KEEP)  { khi = pk1; c_khi = n1; vhi = p1; }
                else { klo = pk1; c_klo = n1; vlo = p1;
                       khi = pk2; c_khi = n2; vhi = p2; }
                ++iter;
                continue;
            }
            // fall through to single probe with pk1
        }

        // Single-pivot round (secant or bisection fallback).
        unsigned pk;
        if (interp) {
            float fr = ((float)c_klo - (float)KEEP) / ((float)c_klo - (float)c_khi);
            pk = f2key(__float_as_uint(vlo + (vhi - vlo) * fr));
        } else {
            pk = (unsigned)((klo + khi) >> 1);
        }
        if ((unsigned long long)pk <= klo) pk = (unsigned)(klo + 1ULL);
        if ((unsigned long long)pk >= khi) pk = (unsigned)(khi - 1ULL);
        float p = key2f(pk);

        unsigned c = 0;
#pragma unroll
        for (int i = 0; i < EPT; ++i) c += (v[i] >= p) ? 1u : 0u;
        c = block_sum(c, scnt[par], lane, warp);
        par ^= 1;

        if (c == KEEP) { T = p; resolved = true; break; }
        if (c > KEEP) { klo = pk; c_klo = c; vlo = p; }
        else          { khi = pk; c_khi = c; vhi = p; }
        ++iter;
    }

    if (!resolved) {
        // khi == klo + 1; c_klo = #{v >= T}.
        T = key2f((unsigned)klo);
        unsigned cGT = 0;
#pragma unroll
        for (int i = 0; i < EPT; ++i) cGT += (v[i] > T) ? 1u : 0u;
        cGT = block_sum(cGT, scnt[par], lane, warp);
        par ^= 1;

        unsigned kk = KEEP - cGT;
        unsigned E  = c_klo - cGT;
        if (E != kk) {
            // cutoff = max{c : #{v == T && idx >= c} >= kk}
            unsigned clo = 0u, chi = FEAT - 1u;
            while (clo < chi) {
                unsigned d  = chi - clo;
                unsigned cm = clo + (d >> 1) + (d & 1u);
                unsigned c  = 0;
#pragma unroll
                for (int i = 0; i < EPT; ++i) {
                    unsigned idx = 4u * (unsigned)tid + 1024u * (unsigned)(i >> 2) + (unsigned)(i & 3);
                    c += (v[i] == T && idx >= cm) ? 1u : 0u;
                }
                c = block_sum(c, scnt[par], lane, warp);
                par ^= 1;
                if (c >= kk) clo = cm; else chi = cm - 1u;
            }
            cutoff = clo;
        }
    }

    // Output (cutoff block-uniform -> uniform branch).
    if (cutoff == 0u) {
#pragma unroll
        for (int j = 0; j < 4; ++j) {
            float4 o;
            o.x = (v[4 * j + 0] >= T) ? v[4 * j + 0] * 2.0f : 0.0f;
            o.y = (v[4 * j + 1] >= T) ? v[4 * j + 1] * 2.0f : 0.0f;
            o.z = (v[4 * j + 2] >= T) ? v[4 * j + 2] * 2.0f : 0.0f;
            o.w = (v[4 * j + 3] >= T) ? v[4 * j + 3] * 2.0f : 0.0f;
            out4[tid + THREADS * j] = o;
        }
    } else {
#pragma unroll
        for (int j = 0; j < 4; ++j) {
            unsigned ib = 4u * (unsigned)tid + 1024u * (unsigned)j;
            float4 o;
            float* po = &o.x;
#pragma unroll
            for (int i = 0; i < 4; ++i) {
                float x = v[4 * j + i];
                bool keep = (x > T) || (x == T && (ib + i) >= cutoff);
                po[i] = keep ? x * 2.0f : 0.0f;
            }
            out4[tid + THREADS * j] = o;
        }
    }
}

extern "C" void kernel_launch(void* const* d_in, const int* in_sizes, int n_in,
                              void* d_out, int out_size) {
    const float* feat = (const float*)d_in[0];
    float* out = (float*)d_out;
    int nrows = in_sizes[0] / FEAT;
    maxout_sel_kernel<<<nrows, THREADS>>>(feat, out);
}